// round 15
// baseline (speedup 1.0000x reference)
#include <cuda_runtime.h>
#include <cuda_fp16.h>

#define FOUT 64
#define KTOT 256
#define NMAX 100000
#define EMAX 3200000
#define GB_ROWS 128
#define CAP 96   // slots per node; Poisson(32) exceeds this with p~1e-26 (overflow path keeps correctness)

// ---------------- scratch (device globals) ----------------
__device__ __align__(256) __half g_hh[NMAX * FOUT];      // 12.8 MB: h = xW (fp16)
__device__ __align__(256) int    g_slot[NMAX * CAP];     // 38.4 MB: per-node src slots
__device__ int   g_cursor[NMAX];                         // per-node edge count (zeroed by aggregate tail)
__device__ int   g_ovf_src[EMAX];
__device__ int   g_ovf_dst[EMAX];
__device__ int   g_ovf_cnt;
__device__ float g_asrc[NMAX];
__device__ float g_adst[NMAX];

// ---------------- kernel 0: reset overflow cursor ----------------
__global__ void zero_ovf() {
    if (threadIdx.x == 0) g_ovf_cnt = 0;
}

__device__ __forceinline__ void place_edge(int src, int dst) {
    int pos = atomicAdd(&g_cursor[dst], 1);
    if (pos < CAP) {
        g_slot[dst * CAP + pos] = src;
    } else {
        int o = atomicAdd(&g_ovf_cnt, 1);
        g_ovf_src[o] = src;
        g_ovf_dst[o] = dst;
    }
}

// ---------------- kernel 1: direct scatter into fixed-capacity slots (4 edges/thread) ----------------
__global__ void scatter_direct(const int* __restrict__ ei, int e) {
    int g = blockIdx.x * blockDim.x + threadIdx.x;
    int nq = e >> 2;
    if (g < nq) {
        int4 s = reinterpret_cast<const int4*>(ei)[g];
        int4 d = reinterpret_cast<const int4*>(ei + e)[g];
        place_edge(s.x, d.x);
        place_edge(s.y, d.y);
        place_edge(s.z, d.z);
        place_edge(s.w, d.w);
    } else {
        int base = nq * 4 + (g - nq);
        if (base < e && g - nq < 4) place_edge(ei[base], ei[e + base]);
    }
}

// ---------------- kernel 2: tensor-core GEMM (tf32 mma.m16n8k8) ----------------
__global__ __launch_bounds__(256) void gemm_tc(
    const float* __restrict__ x, const float* __restrict__ W,
    const float* __restrict__ att_src, const float* __restrict__ att_dst, int n)
{
    __shared__ unsigned xs[GB_ROWS][36];
    __shared__ unsigned ws[32][72];

    int tid = threadIdx.x;
    int lane = tid & 31;
    int w = tid >> 5;
    int g = lane >> 2;
    int c = lane & 3;
    int row0 = blockIdx.x * GB_ROWS;
    int wrow = w * 16;

    float d[8][4];
#pragma unroll
    for (int nt = 0; nt < 8; nt++)
#pragma unroll
        for (int j = 0; j < 4; j++) d[nt][j] = 0.f;

    for (int k0 = 0; k0 < KTOT; k0 += 32) {
#pragma unroll
        for (int i = 0; i < 4; i++) {
            int idx = tid + i * 256;
            int r = idx >> 3;
            int cc = (idx & 7) * 4;
            float4 v = make_float4(0.f, 0.f, 0.f, 0.f);
            if (row0 + r < n)
                v = *reinterpret_cast<const float4*>(&x[(size_t)(row0 + r) * KTOT + k0 + cc]);
            uint4 u;
            asm("cvt.rna.tf32.f32 %0, %1;" : "=r"(u.x) : "f"(v.x));
            asm("cvt.rna.tf32.f32 %0, %1;" : "=r"(u.y) : "f"(v.y));
            asm("cvt.rna.tf32.f32 %0, %1;" : "=r"(u.z) : "f"(v.z));
            asm("cvt.rna.tf32.f32 %0, %1;" : "=r"(u.w) : "f"(v.w));
            *reinterpret_cast<uint4*>(&xs[r][cc]) = u;
        }
#pragma unroll
        for (int i = 0; i < 2; i++) {
            int idx = tid + i * 256;
            int r = idx >> 4;
            int cc = (idx & 15) * 4;
            float4 v = *reinterpret_cast<const float4*>(&W[(size_t)(k0 + r) * FOUT + cc]);
            uint4 u;
            asm("cvt.rna.tf32.f32 %0, %1;" : "=r"(u.x) : "f"(v.x));
            asm("cvt.rna.tf32.f32 %0, %1;" : "=r"(u.y) : "f"(v.y));
            asm("cvt.rna.tf32.f32 %0, %1;" : "=r"(u.z) : "f"(v.z));
            asm("cvt.rna.tf32.f32 %0, %1;" : "=r"(u.w) : "f"(v.w));
            *reinterpret_cast<uint4*>(&ws[r][cc]) = u;
        }
        __syncthreads();

#pragma unroll
        for (int ks = 0; ks < 4; ks++) {
            unsigned a0 = xs[wrow + g][ks * 8 + c];
            unsigned a1 = xs[wrow + g + 8][ks * 8 + c];
            unsigned a2 = xs[wrow + g][ks * 8 + c + 4];
            unsigned a3 = xs[wrow + g + 8][ks * 8 + c + 4];
#pragma unroll
            for (int nt = 0; nt < 8; nt++) {
                unsigned b0 = ws[ks * 8 + c][nt * 8 + g];
                unsigned b1 = ws[ks * 8 + c + 4][nt * 8 + g];
                asm("mma.sync.aligned.m16n8k8.row.col.f32.tf32.tf32.f32 "
                    "{%0,%1,%2,%3}, {%4,%5,%6,%7}, {%8,%9}, {%0,%1,%2,%3};"
                    : "+f"(d[nt][0]), "+f"(d[nt][1]), "+f"(d[nt][2]), "+f"(d[nt][3])
                    : "r"(a0), "r"(a1), "r"(a2), "r"(a3), "r"(b0), "r"(b1));
            }
        }
        __syncthreads();
    }

    float as_v[16], ad_v[16];
#pragma unroll
    for (int nt = 0; nt < 8; nt++) {
        as_v[nt * 2 + 0] = att_src[nt * 8 + 2 * c + 0];
        as_v[nt * 2 + 1] = att_src[nt * 8 + 2 * c + 1];
        ad_v[nt * 2 + 0] = att_dst[nt * 8 + 2 * c + 0];
        ad_v[nt * 2 + 1] = att_dst[nt * 8 + 2 * c + 1];
    }

    float ps1 = 0.f, pd1 = 0.f, ps2 = 0.f, pd2 = 0.f;
#pragma unroll
    for (int nt = 0; nt < 8; nt++) {
        ps1 += d[nt][0] * as_v[2 * nt] + d[nt][1] * as_v[2 * nt + 1];
        pd1 += d[nt][0] * ad_v[2 * nt] + d[nt][1] * ad_v[2 * nt + 1];
        ps2 += d[nt][2] * as_v[2 * nt] + d[nt][3] * as_v[2 * nt + 1];
        pd2 += d[nt][2] * ad_v[2 * nt] + d[nt][3] * ad_v[2 * nt + 1];
    }
#pragma unroll
    for (int o = 1; o < 4; o <<= 1) {
        ps1 += __shfl_xor_sync(0xffffffffu, ps1, o);
        pd1 += __shfl_xor_sync(0xffffffffu, pd1, o);
        ps2 += __shfl_xor_sync(0xffffffffu, ps2, o);
        pd2 += __shfl_xor_sync(0xffffffffu, pd2, o);
    }

    int r1 = row0 + wrow + g;
    int r2 = r1 + 8;
    if (c == 0) {
        if (r1 < n) { g_asrc[r1] = ps1; g_adst[r1] = pd1; }
        if (r2 < n) { g_asrc[r2] = ps2; g_adst[r2] = pd2; }
    }
    if (r1 < n) {
#pragma unroll
        for (int nt = 0; nt < 8; nt++) {
            __half2 h = __float22half2_rn(make_float2(d[nt][0], d[nt][1]));
            *reinterpret_cast<__half2*>(&g_hh[(size_t)r1 * FOUT + nt * 8 + 2 * c]) = h;
        }
    }
    if (r2 < n) {
#pragma unroll
        for (int nt = 0; nt < 8; nt++) {
            __half2 h = __float22half2_rn(make_float2(d[nt][2], d[nt][3]));
            *reinterpret_cast<__half2*>(&g_hh[(size_t)r2 * FOUT + nt * 8 + 2 * c]) = h;
        }
    }
}

// ---------------- kernel 3: gather aggregation over fixed-stride slots ----------------
// Per-warp node; branchless 32-wide batches; cursor self-reset at tail (next call's zero).
__global__ __launch_bounds__(256) void aggregate_kernel(
    float* __restrict__ out, const float* __restrict__ bias, int n)
{
    __shared__ int2 sp[8][32];   // (src, p-bits)

    int w = threadIdx.x >> 5;
    int lane = threadIdx.x & 31;
    int half = lane >> 4;
    int l = lane & 15;
    int node = blockIdx.x * 8 + w;
    if (node >= n) return;

    int cnt = g_cursor[node];
    int ncap = min(cnt, CAP);
    int rs = node * CAP;
    float adst = g_adst[node];

    float4 acc = make_float4(0.f, 0.f, 0.f, 0.f);
    float dsum = 0.f;

    for (int base = 0; base < ncap; base += 32) {
        int idx = base + lane;
        bool ok = idx < ncap;
        int s = ok ? g_slot[rs + idx] : 0;
        float v = g_asrc[s] + adst;
        v = v > 0.f ? v : 0.2f * v;
        float p = ok ? __expf(v) : 0.f;
        dsum += p;
        sp[w][lane] = make_int2(s, __float_as_int(p));
        __syncwarp();
#pragma unroll
        for (int t = 0; t < 32; t += 2) {
            int2 e2 = sp[w][t + half];
            int st = e2.x;
            float pt = __int_as_float(e2.y);
            uint2 hv = *reinterpret_cast<const uint2*>(&g_hh[(size_t)st * FOUT + l * 4]);
            float2 f01 = __half22float2(*reinterpret_cast<__half2*>(&hv.x));
            float2 f23 = __half22float2(*reinterpret_cast<__half2*>(&hv.y));
            acc.x += pt * f01.x; acc.y += pt * f01.y;
            acc.z += pt * f23.x; acc.w += pt * f23.y;
        }
        __syncwarp();
    }

    // self-loop (half 0 only)
    if (half == 0) {
        float v = g_asrc[node] + adst;
        v = v > 0.f ? v : 0.2f * v;
        float p = __expf(v);
        if (l == 0) dsum += p;
        uint2 hv = *reinterpret_cast<const uint2*>(&g_hh[(size_t)node * FOUT + l * 4]);
        float2 f01 = __half22float2(*reinterpret_cast<__half2*>(&hv.x));
        float2 f23 = __half22float2(*reinterpret_cast<__half2*>(&hv.y));
        acc.x += p * f01.x; acc.y += p * f01.y;
        acc.z += p * f23.x; acc.w += p * f23.y;
    }

    // overflow edges (essentially never taken; correctness path)
    if (cnt > CAP) {
        int ovfn = g_ovf_cnt;
        for (int j = 0; j < ovfn; j++) {
            if (g_ovf_dst[j] == node) {
                int s = g_ovf_src[j];
                float v = g_asrc[s] + adst;
                v = v > 0.f ? v : 0.2f * v;
                float p = __expf(v);
                if (half == 0) {
                    if (l == 0) dsum += p;
                    uint2 hv = *reinterpret_cast<const uint2*>(&g_hh[(size_t)s * FOUT + l * 4]);
                    float2 f01 = __half22float2(*reinterpret_cast<__half2*>(&hv.x));
                    float2 f23 = __half22float2(*reinterpret_cast<__half2*>(&hv.y));
                    acc.x += p * f01.x; acc.y += p * f01.y;
                    acc.z += p * f23.x; acc.w += p * f23.y;
                }
            }
        }
    }

#pragma unroll
    for (int o = 16; o > 0; o >>= 1)
        dsum += __shfl_xor_sync(0xffffffffu, dsum, o);

    acc.x += __shfl_down_sync(0xffffffffu, acc.x, 16);
    acc.y += __shfl_down_sync(0xffffffffu, acc.y, 16);
    acc.z += __shfl_down_sync(0xffffffffu, acc.z, 16);
    acc.w += __shfl_down_sync(0xffffffffu, acc.w, 16);

    if (half == 0) {
        float inv = 1.0f / (dsum + 1e-16f);
        float4 b = reinterpret_cast<const float4*>(bias)[l];
        reinterpret_cast<float4*>(out)[(size_t)node * 16 + l] =
            make_float4(acc.x * inv + b.x, acc.y * inv + b.y,
                        acc.z * inv + b.z, acc.w * inv + b.w);
    }

    // reset cursor for the next call (first call relies on static zero-init)
    if (lane == 0) g_cursor[node] = 0;
}

// ---------------- launch: fork GEMM ∥ scatter, join before aggregate ----------------
extern "C" void kernel_launch(void* const* d_in, const int* in_sizes, int n_in,
                              void* d_out, int out_size) {
    const float* x       = (const float*)d_in[0];
    const int*   ei      = (const int*)d_in[1];
    const float* W       = (const float*)d_in[2];
    const float* att_src = (const float*)d_in[3];
    const float* att_dst = (const float*)d_in[4];
    const float* bias    = (const float*)d_in[5];
    float* out = (float*)d_out;

    int n = in_sizes[0] / KTOT;   // 100000
    int e = in_sizes[1] / 2;      // 3200000

    static cudaStream_t s2 = nullptr;
    static cudaEvent_t evFork = nullptr, evJoin = nullptr;
    if (s2 == nullptr) {
        cudaStreamCreateWithFlags(&s2, cudaStreamNonBlocking);
        cudaEventCreateWithFlags(&evFork, cudaEventDisableTiming);
        cudaEventCreateWithFlags(&evJoin, cudaEventDisableTiming);
    }

    cudaEventRecord(evFork, 0);
    cudaStreamWaitEvent(s2, evFork, 0);

    int nq = e / 4 + 4;
    zero_ovf<<<1, 32>>>();                                    // launch 0
    scatter_direct<<<(nq + 255) / 256, 256>>>(ei, e);         // launch 1
    gemm_tc<<<(n + GB_ROWS - 1) / GB_ROWS, 256, 0, s2>>>(     // launch 2 (side stream)
        x, W, att_src, att_dst, n);
    cudaEventRecord(evJoin, s2);
    cudaStreamWaitEvent(0, evJoin, 0);
    aggregate_kernel<<<(n + 7) / 8, 256>>>(out, bias, n);     // launch 3 (profiled slot)
}

// round 16
// speedup vs baseline: 1.0002x; 1.0002x over previous
#include <cuda_runtime.h>
#include <cuda_fp16.h>

#define FOUT 64
#define KTOT 256
#define NMAX 100000
#define EMAX 3200000
#define GB_ROWS 128
#define CAP 96   // slots per node; Poisson(32) exceeds this with p~1e-26 (overflow path keeps correctness)

// ---------------- scratch (device globals) ----------------
__device__ __align__(256) float g_h[NMAX * FOUT];        // 25.6 MB: h = xW (fp32)
__device__ __align__(256) int   g_slot[NMAX * CAP];      // 38.4 MB: per-node src slots
__device__ int   g_cursor[NMAX];                         // per-node edge count (zeroed by aggregate tail)
__device__ int   g_ovf_src[EMAX];
__device__ int   g_ovf_dst[EMAX];
__device__ int   g_ovf_cnt;
__device__ float g_asrc[NMAX];
__device__ float g_adst[NMAX];

#define FMA2(acc, w, xv) \
    asm("fma.rn.f32x2 %0, %1, %2, %0;" : "+l"(acc) : "l"(w), "l"(xv))

// ---------------- kernel 0: reset overflow cursor ----------------
__global__ void zero_ovf() {
    if (threadIdx.x == 0) g_ovf_cnt = 0;
}

__device__ __forceinline__ void place_edge(int src, int dst) {
    int pos = atomicAdd(&g_cursor[dst], 1);
    if (pos < CAP) {
        g_slot[dst * CAP + pos] = src;
    } else {
        int o = atomicAdd(&g_ovf_cnt, 1);
        g_ovf_src[o] = src;
        g_ovf_dst[o] = dst;
    }
}

// ---------------- kernel 1: direct scatter into fixed-capacity slots (4 edges/thread) ----------------
__global__ void scatter_direct(const int* __restrict__ ei, int e) {
    int g = blockIdx.x * blockDim.x + threadIdx.x;
    int nq = e >> 2;
    if (g < nq) {
        int4 s = reinterpret_cast<const int4*>(ei)[g];
        int4 d = reinterpret_cast<const int4*>(ei + e)[g];
        place_edge(s.x, d.x);
        place_edge(s.y, d.y);
        place_edge(s.z, d.z);
        place_edge(s.w, d.w);
    } else {
        int base = nq * 4 + (g - nq);
        if (base < e && g - nq < 4) place_edge(ei[base], ei[e + base]);
    }
}

// ---------------- kernel 2: tensor-core GEMM (tf32 mma.m16n8k8) ----------------
__global__ __launch_bounds__(256) void gemm_tc(
    const float* __restrict__ x, const float* __restrict__ W,
    const float* __restrict__ att_src, const float* __restrict__ att_dst, int n)
{
    __shared__ unsigned xs[GB_ROWS][36];
    __shared__ unsigned ws[32][72];

    int tid = threadIdx.x;
    int lane = tid & 31;
    int w = tid >> 5;
    int g = lane >> 2;
    int c = lane & 3;
    int row0 = blockIdx.x * GB_ROWS;
    int wrow = w * 16;

    float d[8][4];
#pragma unroll
    for (int nt = 0; nt < 8; nt++)
#pragma unroll
        for (int j = 0; j < 4; j++) d[nt][j] = 0.f;

    for (int k0 = 0; k0 < KTOT; k0 += 32) {
#pragma unroll
        for (int i = 0; i < 4; i++) {
            int idx = tid + i * 256;
            int r = idx >> 3;
            int cc = (idx & 7) * 4;
            float4 v = make_float4(0.f, 0.f, 0.f, 0.f);
            if (row0 + r < n)
                v = *reinterpret_cast<const float4*>(&x[(size_t)(row0 + r) * KTOT + k0 + cc]);
            uint4 u;
            asm("cvt.rna.tf32.f32 %0, %1;" : "=r"(u.x) : "f"(v.x));
            asm("cvt.rna.tf32.f32 %0, %1;" : "=r"(u.y) : "f"(v.y));
            asm("cvt.rna.tf32.f32 %0, %1;" : "=r"(u.z) : "f"(v.z));
            asm("cvt.rna.tf32.f32 %0, %1;" : "=r"(u.w) : "f"(v.w));
            *reinterpret_cast<uint4*>(&xs[r][cc]) = u;
        }
#pragma unroll
        for (int i = 0; i < 2; i++) {
            int idx = tid + i * 256;
            int r = idx >> 4;
            int cc = (idx & 15) * 4;
            float4 v = *reinterpret_cast<const float4*>(&W[(size_t)(k0 + r) * FOUT + cc]);
            uint4 u;
            asm("cvt.rna.tf32.f32 %0, %1;" : "=r"(u.x) : "f"(v.x));
            asm("cvt.rna.tf32.f32 %0, %1;" : "=r"(u.y) : "f"(v.y));
            asm("cvt.rna.tf32.f32 %0, %1;" : "=r"(u.z) : "f"(v.z));
            asm("cvt.rna.tf32.f32 %0, %1;" : "=r"(u.w) : "f"(v.w));
            *reinterpret_cast<uint4*>(&ws[r][cc]) = u;
        }
        __syncthreads();

#pragma unroll
        for (int ks = 0; ks < 4; ks++) {
            unsigned a0 = xs[wrow + g][ks * 8 + c];
            unsigned a1 = xs[wrow + g + 8][ks * 8 + c];
            unsigned a2 = xs[wrow + g][ks * 8 + c + 4];
            unsigned a3 = xs[wrow + g + 8][ks * 8 + c + 4];
#pragma unroll
            for (int nt = 0; nt < 8; nt++) {
                unsigned b0 = ws[ks * 8 + c][nt * 8 + g];
                unsigned b1 = ws[ks * 8 + c + 4][nt * 8 + g];
                asm("mma.sync.aligned.m16n8k8.row.col.f32.tf32.tf32.f32 "
                    "{%0,%1,%2,%3}, {%4,%5,%6,%7}, {%8,%9}, {%0,%1,%2,%3};"
                    : "+f"(d[nt][0]), "+f"(d[nt][1]), "+f"(d[nt][2]), "+f"(d[nt][3])
                    : "r"(a0), "r"(a1), "r"(a2), "r"(a3), "r"(b0), "r"(b1));
            }
        }
        __syncthreads();
    }

    float as_v[16], ad_v[16];
#pragma unroll
    for (int nt = 0; nt < 8; nt++) {
        as_v[nt * 2 + 0] = att_src[nt * 8 + 2 * c + 0];
        as_v[nt * 2 + 1] = att_src[nt * 8 + 2 * c + 1];
        ad_v[nt * 2 + 0] = att_dst[nt * 8 + 2 * c + 0];
        ad_v[nt * 2 + 1] = att_dst[nt * 8 + 2 * c + 1];
    }

    float ps1 = 0.f, pd1 = 0.f, ps2 = 0.f, pd2 = 0.f;
#pragma unroll
    for (int nt = 0; nt < 8; nt++) {
        ps1 += d[nt][0] * as_v[2 * nt] + d[nt][1] * as_v[2 * nt + 1];
        pd1 += d[nt][0] * ad_v[2 * nt] + d[nt][1] * ad_v[2 * nt + 1];
        ps2 += d[nt][2] * as_v[2 * nt] + d[nt][3] * as_v[2 * nt + 1];
        pd2 += d[nt][2] * ad_v[2 * nt] + d[nt][3] * ad_v[2 * nt + 1];
    }
#pragma unroll
    for (int o = 1; o < 4; o <<= 1) {
        ps1 += __shfl_xor_sync(0xffffffffu, ps1, o);
        pd1 += __shfl_xor_sync(0xffffffffu, pd1, o);
        ps2 += __shfl_xor_sync(0xffffffffu, ps2, o);
        pd2 += __shfl_xor_sync(0xffffffffu, pd2, o);
    }

    int r1 = row0 + wrow + g;
    int r2 = r1 + 8;
    if (c == 0) {
        if (r1 < n) { g_asrc[r1] = ps1; g_adst[r1] = pd1; }
        if (r2 < n) { g_asrc[r2] = ps2; g_adst[r2] = pd2; }
    }
    if (r1 < n) {
#pragma unroll
        for (int nt = 0; nt < 8; nt++)
            *reinterpret_cast<float2*>(&g_h[(size_t)r1 * FOUT + nt * 8 + 2 * c]) =
                make_float2(d[nt][0], d[nt][1]);
    }
    if (r2 < n) {
#pragma unroll
        for (int nt = 0; nt < 8; nt++)
            *reinterpret_cast<float2*>(&g_h[(size_t)r2 * FOUT + nt * 8 + 2 * c]) =
                make_float2(d[nt][2], d[nt][3]);
    }
}

// ---------------- kernel 3: gather aggregation, fp32 h + packed FMA2 ----------------
__global__ __launch_bounds__(256) void aggregate_kernel(
    float* __restrict__ out, const float* __restrict__ bias, int n)
{
    __shared__ int2 sp[8][32];   // (src, p-bits)

    int w = threadIdx.x >> 5;
    int lane = threadIdx.x & 31;
    int half = lane >> 4;
    int l = lane & 15;
    int node = blockIdx.x * 8 + w;
    if (node >= n) return;

    int cnt = g_cursor[node];
    int ncap = min(cnt, CAP);
    int rs = node * CAP;
    float adst = g_adst[node];

    unsigned long long a01 = 0ull, a23 = 0ull;   // packed fp32 pairs
    float dsum = 0.f;
    const ulonglong2* __restrict__ h2p = reinterpret_cast<const ulonglong2*>(g_h);

    for (int base = 0; base < ncap; base += 32) {
        int idx = base + lane;
        bool ok = idx < ncap;
        int s = ok ? g_slot[rs + idx] : 0;
        float v = g_asrc[s] + adst;
        v = v > 0.f ? v : 0.2f * v;
        float p = ok ? __expf(v) : 0.f;
        dsum += p;
        sp[w][lane] = make_int2(s, __float_as_int(p));
        __syncwarp();
#pragma unroll
        for (int t = 0; t < 32; t += 2) {
            int2 e2 = sp[w][t + half];
            float pt = __int_as_float(e2.y);
            unsigned long long ptd;
            asm("mov.b64 %0, {%1, %1};" : "=l"(ptd) : "r"(__float_as_uint(pt)));
            // lane l of 16 loads 16B (4 floats) of the 256-B row
            ulonglong2 hv = h2p[(size_t)e2.x * 16 + l];
            FMA2(a01, hv.x, ptd);
            FMA2(a23, hv.y, ptd);
        }
        __syncwarp();
    }

    float4 acc;
    asm("mov.b64 {%0, %1}, %2;" : "=f"(acc.x), "=f"(acc.y) : "l"(a01));
    asm("mov.b64 {%0, %1}, %2;" : "=f"(acc.z), "=f"(acc.w) : "l"(a23));

    // self-loop (half 0 only)
    if (half == 0) {
        float v = g_asrc[node] + adst;
        v = v > 0.f ? v : 0.2f * v;
        float p = __expf(v);
        if (l == 0) dsum += p;
        float4 hv = reinterpret_cast<const float4*>(g_h)[(size_t)node * 16 + l];
        acc.x += p * hv.x; acc.y += p * hv.y;
        acc.z += p * hv.z; acc.w += p * hv.w;
    }

    // overflow edges (essentially never taken; correctness path)
    if (cnt > CAP) {
        int ovfn = g_ovf_cnt;
        for (int j = 0; j < ovfn; j++) {
            if (g_ovf_dst[j] == node) {
                int s = g_ovf_src[j];
                float v = g_asrc[s] + adst;
                v = v > 0.f ? v : 0.2f * v;
                float p = __expf(v);
                if (half == 0) {
                    if (l == 0) dsum += p;
                    float4 hv = reinterpret_cast<const float4*>(g_h)[(size_t)s * 16 + l];
                    acc.x += p * hv.x; acc.y += p * hv.y;
                    acc.z += p * hv.z; acc.w += p * hv.w;
                }
            }
        }
    }

#pragma unroll
    for (int o = 16; o > 0; o >>= 1)
        dsum += __shfl_xor_sync(0xffffffffu, dsum, o);

    acc.x += __shfl_down_sync(0xffffffffu, acc.x, 16);
    acc.y += __shfl_down_sync(0xffffffffu, acc.y, 16);
    acc.z += __shfl_down_sync(0xffffffffu, acc.z, 16);
    acc.w += __shfl_down_sync(0xffffffffu, acc.w, 16);

    if (half == 0) {
        float inv = 1.0f / (dsum + 1e-16f);
        float4 b = reinterpret_cast<const float4*>(bias)[l];
        reinterpret_cast<float4*>(out)[(size_t)node * 16 + l] =
            make_float4(acc.x * inv + b.x, acc.y * inv + b.y,
                        acc.z * inv + b.z, acc.w * inv + b.w);
    }

    // reset cursor for the next call (first call relies on static zero-init)
    if (lane == 0) g_cursor[node] = 0;
}

// ---------------- launch: fork GEMM ∥ scatter, join before aggregate ----------------
extern "C" void kernel_launch(void* const* d_in, const int* in_sizes, int n_in,
                              void* d_out, int out_size) {
    const float* x       = (const float*)d_in[0];
    const int*   ei      = (const int*)d_in[1];
    const float* W       = (const float*)d_in[2];
    const float* att_src = (const float*)d_in[3];
    const float* att_dst = (const float*)d_in[4];
    const float* bias    = (const float*)d_in[5];
    float* out = (float*)d_out;

    int n = in_sizes[0] / KTOT;   // 100000
    int e = in_sizes[1] / 2;      // 3200000

    static cudaStream_t s2 = nullptr;
    static cudaEvent_t evFork = nullptr, evJoin = nullptr;
    if (s2 == nullptr) {
        cudaStreamCreateWithFlags(&s2, cudaStreamNonBlocking);
        cudaEventCreateWithFlags(&evFork, cudaEventDisableTiming);
        cudaEventCreateWithFlags(&evJoin, cudaEventDisableTiming);
    }

    cudaEventRecord(evFork, 0);
    cudaStreamWaitEvent(s2, evFork, 0);

    int nq = e / 4 + 4;
    zero_ovf<<<1, 32>>>();                                    // launch 0
    scatter_direct<<<(nq + 255) / 256, 256>>>(ei, e);         // launch 1
    gemm_tc<<<(n + GB_ROWS - 1) / GB_ROWS, 256, 0, s2>>>(     // launch 2 (side stream)
        x, W, att_src, att_dst, n);
    cudaEventRecord(evJoin, s2);
    cudaStreamWaitEvent(0, evJoin, 0);
    aggregate_kernel<<<(n + 7) / 8, 256>>>(out, bias, n);     // launch 3 (profiled slot)
}